// round 1
// baseline (speedup 1.0000x reference)
#include <cuda_runtime.h>

#define BB 32
#define CC 512
#define C8 64
#define NPIX 4096
#define CHUNK 512
#define NT 128
#define CT 64
#define NCHUNKS (NPIX/CHUNK)   // 8
#define NTILES  (CHUNK/NT)     // 4
#define CTILES  (CC/CT)        // 8

// Scratch (device globals — no allocation allowed)
__device__ float g_logits[BB*C8*C8];   // per-batch QK^T accumulators
__device__ float g_xsum[BB*CC];        // per-batch per-channel pixel sums
__device__ float g_wqT[CC*C8];         // transposed weights [c][o]
__device__ float g_wkT[CC*C8];

// -------------------------------------------------------------------------
// prep: zero accumulators + transpose wq/wk to [c][o] for coalesced smem fill
// -------------------------------------------------------------------------
__global__ void prep_kernel(const float* __restrict__ wq,
                            const float* __restrict__ wk) {
    int t = blockIdx.x * blockDim.x + threadIdx.x;
    int S = gridDim.x * blockDim.x;
    for (int i = t; i < BB*C8*C8; i += S) g_logits[i] = 0.f;
    for (int i = t; i < BB*CC;    i += S) g_xsum[i]   = 0.f;
    for (int i = t; i < CC*C8;    i += S) {
        int c = i >> 6, o = i & 63;
        g_wqT[i] = wq[o*CC + c];
        g_wkT[i] = wk[o*CC + c];
    }
}

// -------------------------------------------------------------------------
// main: per (batch, pixel-chunk) CTA.
//   phase 1 per n-tile: q,k = W{q,k} @ x_tile  (register-tiled fp32 GEMM)
//   phase 2 per n-tile: logits += q @ k^T      (via smem round-trip)
//   by-product: per-channel x sums for vmean.
// smem (floats): [0..8192) x_s[64][128] | [8192..12288) wq_s[64][64]
//                [12288..16384) wk_s    | phase2 alias: q_s[64][129] @0,
//                k_s[64][129] @8256     | [16512..17024) xsum_s[512]
// -------------------------------------------------------------------------
#define SMEM_FLOATS 17024
#define SMEM_BYTES  (SMEM_FLOATS * 4)

__global__ void __launch_bounds__(256, 2)
logits_kernel(const float* __restrict__ x,
              const float* __restrict__ bq,
              const float* __restrict__ bk)
{
    extern __shared__ float sm[];
    float* x_s    = sm;            // [64][128]
    float* wq_s   = sm + 8192;     // [64][64]
    float* wk_s   = sm + 12288;    // [64][64]
    float* q_s    = sm;            // [64][129] (phase 2 alias)
    float* k_s    = sm + 8256;     // [64][129]
    float* xsum_s = sm + 16512;    // [512]

    const int tid = threadIdx.x;
    const int b = blockIdx.y;
    const int n_chunk = blockIdx.x * CHUNK;

    const int tx = tid & 15;
    const int ty = tid >> 4;
    const int o0 = ty * 4;   // 4 output rows per thread
    const int n0 = tx * 8;   // 8 pixels per thread (phase 1)
    const int p0 = tx * 4;   // 4 logit cols per thread (phase 2)

    const int c_local = tid >> 2;  // 0..63 (x-tile row owned for loading)
    const int quad    = tid & 3;

    xsum_s[tid]       = 0.f;
    xsum_s[tid + 256] = 0.f;

    float lacc[4][4];
    #pragma unroll
    for (int i = 0; i < 4; i++)
        #pragma unroll
        for (int j = 0; j < 4; j++) lacc[i][j] = 0.f;

    float bq4[4], bk4[4];
    #pragma unroll
    for (int i = 0; i < 4; i++) { bq4[i] = bq[o0+i]; bk4[i] = bk[o0+i]; }

    for (int nt = 0; nt < NTILES; ++nt) {
        const int n_base = n_chunk + nt * NT;

        float qa[4][8], ka[4][8];
        #pragma unroll
        for (int i = 0; i < 4; i++)
            #pragma unroll
            for (int j = 0; j < 8; j++) { qa[i][j] = 0.f; ka[i][j] = 0.f; }

        for (int ct = 0; ct < CTILES; ++ct) {
            __syncthreads();  // prior-phase smem reads complete

            // --- load x tile [64c][128n], accumulate channel sums ---
            const float* xg = x + ((size_t)b*CC + (size_t)(ct*CT + c_local))*NPIX + n_base;
            float psum = 0.f;
            #pragma unroll
            for (int k2 = 0; k2 < 8; ++k2) {
                int noff = quad*4 + k2*16;
                float4 v = *(const float4*)(xg + noff);
                *(float4*)&x_s[c_local*NT + noff] = v;
                psum += v.x + v.y + v.z + v.w;
            }
            atomicAdd(&xsum_s[ct*CT + c_local], psum);

            // --- load weight tiles [64c][64o] (pre-transposed) ---
            #pragma unroll
            for (int i = 0; i < 4; ++i) {
                int idx = tid + i*256;             // 0..1023
                int cr  = idx >> 4;
                int seg = (idx & 15) * 4;
                *(float4*)&wq_s[cr*C8 + seg] = *(const float4*)&g_wqT[(ct*CT+cr)*C8 + seg];
                *(float4*)&wk_s[cr*C8 + seg] = *(const float4*)&g_wkT[(ct*CT+cr)*C8 + seg];
            }
            __syncthreads();

            // --- projection FMAs: 64 per thread per c-step ---
            #pragma unroll 8
            for (int c = 0; c < CT; ++c) {
                float4 wqv4 = *(const float4*)&wq_s[c*C8 + o0];
                float4 wkv4 = *(const float4*)&wk_s[c*C8 + o0];
                float4 xa   = *(const float4*)&x_s[c*NT + n0];
                float4 xb   = *(const float4*)&x_s[c*NT + n0 + 4];
                float xv[8]  = {xa.x, xa.y, xa.z, xa.w, xb.x, xb.y, xb.z, xb.w};
                float wqv[4] = {wqv4.x, wqv4.y, wqv4.z, wqv4.w};
                float wkv[4] = {wkv4.x, wkv4.y, wkv4.z, wkv4.w};
                #pragma unroll
                for (int i = 0; i < 4; i++)
                    #pragma unroll
                    for (int j = 0; j < 8; j++) {
                        qa[i][j] += wqv[i] * xv[j];
                        ka[i][j] += wkv[i] * xv[j];
                    }
            }
        }
        __syncthreads();

        // --- phase 2: q,k (+bias) -> smem [o][n] stride 129 (conflict-free reads) ---
        #pragma unroll
        for (int i = 0; i < 4; i++)
            #pragma unroll
            for (int j = 0; j < 8; j++) {
                q_s[(o0+i)*129 + n0 + j] = qa[i][j] + bq4[i];
                k_s[(o0+i)*129 + n0 + j] = ka[i][j] + bk4[i];
            }
        __syncthreads();

        // --- logits += q @ k^T over this n-tile ---
        #pragma unroll 4
        for (int n = 0; n < NT; ++n) {
            float la[4], lb[4];
            #pragma unroll
            for (int i = 0; i < 4; i++) la[i] = q_s[(o0+i)*129 + n];
            #pragma unroll
            for (int i = 0; i < 4; i++) lb[i] = k_s[(p0+i)*129 + n];
            #pragma unroll
            for (int i = 0; i < 4; i++)
                #pragma unroll
                for (int j = 0; j < 4; j++) lacc[i][j] += la[i] * lb[j];
        }
    }

    // --- flush partials ---
    float* Lg = g_logits + b*C8*C8;
    #pragma unroll
    for (int i = 0; i < 4; i++)
        #pragma unroll
        for (int j = 0; j < 4; j++)
            atomicAdd(&Lg[(o0+i)*C8 + p0 + j], lacc[i][j]);

    __syncthreads();
    atomicAdd(&g_xsum[b*CC + tid],       xsum_s[tid]);
    atomicAdd(&g_xsum[b*CC + tid + 256], xsum_s[tid + 256]);
}

// -------------------------------------------------------------------------
// finalize: vmean = Wv@xmean + bv; column softmax over o; out = attn @ vmean
// -------------------------------------------------------------------------
__global__ void finalize_kernel(const float* __restrict__ wv,
                                const float* __restrict__ bv,
                                float* __restrict__ out)
{
    __shared__ float vmean_s[C8];
    __shared__ float attn_s[C8][C8 + 1];
    const int b = blockIdx.x;
    const int t = threadIdx.x;  // 0..63

    // vmean[t]
    const float* xs = g_xsum + b*CC;
    float acc = 0.f;
    for (int c = 0; c < CC; ++c) acc += wv[t*CC + c] * xs[c];
    vmean_s[t] = acc * (1.f / NPIX) + bv[t];

    // softmax over o for column t
    const float* Lg = g_logits + b*C8*C8;
    float col[C8];
    float m = -1e30f;
    #pragma unroll
    for (int o = 0; o < C8; ++o) { col[o] = Lg[o*C8 + t]; m = fmaxf(m, col[o]); }
    float s = 0.f;
    #pragma unroll
    for (int o = 0; o < C8; ++o) { col[o] = expf(col[o] - m); s += col[o]; }
    float inv = 1.f / s;
    #pragma unroll
    for (int o = 0; o < C8; ++o) attn_s[o][t] = col[o] * inv;
    __syncthreads();

    // out[b, t] = sum_p attn[t][p] * vmean[p]
    float r = 0.f;
    #pragma unroll
    for (int p = 0; p < C8; ++p) r += attn_s[t][p] * vmean_s[p];
    out[b*C8 + t] = r;
}

// -------------------------------------------------------------------------
extern "C" void kernel_launch(void* const* d_in, const int* in_sizes, int n_in,
                              void* d_out, int out_size) {
    const float* x  = (const float*)d_in[0];
    const float* wq = (const float*)d_in[1];
    const float* bq = (const float*)d_in[2];
    const float* wk = (const float*)d_in[3];
    const float* bk = (const float*)d_in[4];
    const float* wv = (const float*)d_in[5];
    const float* bv = (const float*)d_in[6];
    float* out = (float*)d_out;

    cudaFuncSetAttribute(logits_kernel,
                         cudaFuncAttributeMaxDynamicSharedMemorySize, SMEM_BYTES);

    prep_kernel<<<128, 256>>>(wq, wk);
    logits_kernel<<<dim3(NCHUNKS, BB), 256, SMEM_BYTES>>>(x, bq, bk);
    finalize_kernel<<<BB, C8>>>(wv, bv, out);
}

// round 2
// speedup vs baseline: 1.2094x; 1.2094x over previous
#include <cuda_runtime.h>

#define BB 32
#define CC 512
#define C8 64
#define NPIX 4096
#define NT 128
#define CT 64
#define CTILES (CC/CT)           // 8
#define NITEMS (BB * (NPIX/NT))  // 32 batches * 32 n-tiles = 1024

typedef unsigned long long u64t;

// ---- packed f32x2 helpers (FFMA2 path, sm_100+) ----
__device__ __forceinline__ u64t pack2(float lo, float hi) {
    u64t r; asm("mov.b64 %0, {%1, %2};" : "=l"(r) : "f"(lo), "f"(hi)); return r;
}
__device__ __forceinline__ u64t fma2(u64t a, u64t b, u64t c) {
    u64t d; asm("fma.rn.f32x2 %0, %1, %2, %3;" : "=l"(d) : "l"(a), "l"(b), "l"(c)); return d;
}
__device__ __forceinline__ u64t add2(u64t a, u64t b) {
    u64t d; asm("add.rn.f32x2 %0, %1, %2;" : "=l"(d) : "l"(a), "l"(b)); return d;
}
__device__ __forceinline__ void unpack2(u64t v, float& lo, float& hi) {
    asm("mov.b64 {%0, %1}, %2;" : "=f"(lo), "=f"(hi) : "l"(v));
}

// Scratch (device globals — no allocation allowed)
__device__ float g_logits[BB*C8*C8];
__device__ float g_xsum[BB*CC];
__device__ float g_wqT[CC*C8];     // [c][o]
__device__ float g_wkT[CC*C8];
__device__ unsigned g_ctr;

// -------------------------------------------------------------------------
__global__ void prep_kernel(const float* __restrict__ wq,
                            const float* __restrict__ wk) {
    int t = blockIdx.x * blockDim.x + threadIdx.x;
    int S = gridDim.x * blockDim.x;
    if (t == 0) g_ctr = 0;
    for (int i = t; i < BB*C8*C8; i += S) g_logits[i] = 0.f;
    for (int i = t; i < BB*CC;    i += S) g_xsum[i]   = 0.f;
    for (int i = t; i < CC*C8;    i += S) {
        int c = i >> 6, o = i & 63;
        g_wqT[i] = wq[o*CC + c];
        g_wkT[i] = wk[o*CC + c];
    }
}

// -------------------------------------------------------------------------
// Persistent work-stealing kernel. Item = (batch, 128-px n-tile).
// Phase 1: q,k = W @ x_tile with packed f32x2 FMA (2 MAC/instr).
// Phase 2: logits += q @ k^T, packed along reduction dim.
//
// smem (floats): region A [0..8320): x_s[64][128] (p1) / q_s[64][130] (p2)
//                region B [8320..16640): wq_s@8320,wk_s@12416 (p1) / k_s (p2)
// -------------------------------------------------------------------------
#define SMEM_FLOATS 16640
#define SMEM_BYTES  (SMEM_FLOATS * 4)

__global__ void __launch_bounds__(256, 2)
logits_kernel(const float* __restrict__ x,
              const float* __restrict__ bq,
              const float* __restrict__ bk)
{
    extern __shared__ float sm[];
    float* x_s  = sm;          // [64][128]
    float* wq_s = sm + 8320;   // [64][64]
    float* wk_s = sm + 12416;  // [64][64]
    float* q_s  = sm;          // [64][130]
    float* k_s  = sm + 8320;   // [64][130]
    __shared__ unsigned item_s;

    const int tid = threadIdx.x;
    const int tx = tid & 15;
    const int ty = tid >> 4;
    const int o0 = ty * 4;     // 4 output rows per thread
    const int n0 = tx * 8;     // 8 pixels per thread (phase 1)
    const int p0 = tx * 4;     // 4 logit cols per thread (phase 2)
    const int c_local = tid >> 2;
    const int quad    = tid & 3;

    u64t bq2[4], bk2[4];
    #pragma unroll
    for (int i = 0; i < 4; i++) {
        float vq = bq[o0+i], vk = bk[o0+i];
        bq2[i] = pack2(vq, vq);
        bk2[i] = pack2(vk, vk);
    }

    while (true) {
        if (tid == 0) item_s = atomicAdd(&g_ctr, 1u);
        __syncthreads();
        const unsigned item = item_s;
        if (item >= NITEMS) break;
        const int b = item >> 5;
        const int n_base = (item & 31) * NT;

        u64t qa[4][4], ka[4][4];
        #pragma unroll
        for (int i = 0; i < 4; i++)
            #pragma unroll
            for (int j = 0; j < 4; j++) { qa[i][j] = 0ull; ka[i][j] = 0ull; }

        for (int ct = 0; ct < CTILES; ++ct) {
            __syncthreads();  // prior-phase smem reads complete

            // --- load x tile [64c][128n], channel partial sums ---
            const float* xg = x + ((size_t)b*CC + (size_t)(ct*CT + c_local))*NPIX + n_base;
            float psum = 0.f;
            #pragma unroll
            for (int k2 = 0; k2 < 8; ++k2) {
                int noff = quad*4 + k2*16;
                float4 v = *(const float4*)(xg + noff);
                *(float4*)&x_s[c_local*NT + noff] = v;
                psum += v.x + v.y + v.z + v.w;
            }
            psum += __shfl_xor_sync(0xffffffffu, psum, 1);
            psum += __shfl_xor_sync(0xffffffffu, psum, 2);
            if (quad == 0) atomicAdd(&g_xsum[b*CC + ct*CT + c_local], psum);

            // --- load weight tiles [64c][64o] ---
            #pragma unroll
            for (int i = 0; i < 4; ++i) {
                int idx = tid + i*256;
                int cr  = idx >> 4;
                int seg = (idx & 15) * 4;
                *(float4*)&wq_s[cr*C8 + seg] = *(const float4*)&g_wqT[(ct*CT+cr)*C8 + seg];
                *(float4*)&wk_s[cr*C8 + seg] = *(const float4*)&g_wkT[(ct*CT+cr)*C8 + seg];
            }
            __syncthreads();

            // --- packed projection: 32 FFMA2 per c-step ---
            #pragma unroll 8
            for (int c = 0; c < CT; ++c) {
                float4 wq4 = *(const float4*)&wq_s[c*C8 + o0];
                float4 wk4 = *(const float4*)&wk_s[c*C8 + o0];
                u64t wq2[4], wk2[4];
                wq2[0]=pack2(wq4.x,wq4.x); wq2[1]=pack2(wq4.y,wq4.y);
                wq2[2]=pack2(wq4.z,wq4.z); wq2[3]=pack2(wq4.w,wq4.w);
                wk2[0]=pack2(wk4.x,wk4.x); wk2[1]=pack2(wk4.y,wk4.y);
                wk2[2]=pack2(wk4.z,wk4.z); wk2[3]=pack2(wk4.w,wk4.w);
                ulonglong2 xa = *(const ulonglong2*)&x_s[c*NT + n0];
                ulonglong2 xb = *(const ulonglong2*)&x_s[c*NT + n0 + 4];
                u64t x2[4] = {xa.x, xa.y, xb.x, xb.y};
                #pragma unroll
                for (int i = 0; i < 4; i++)
                    #pragma unroll
                    for (int j = 0; j < 4; j++) {
                        qa[i][j] = fma2(wq2[i], x2[j], qa[i][j]);
                        ka[i][j] = fma2(wk2[i], x2[j], ka[i][j]);
                    }
            }
        }
        __syncthreads();

        // --- q,k (+bias) -> smem [o][n] stride 130, packed pairs along n ---
        #pragma unroll
        for (int i = 0; i < 4; i++)
            #pragma unroll
            for (int j = 0; j < 4; j++) {
                *(u64t*)&q_s[(o0+i)*130 + n0 + 2*j] = add2(qa[i][j], bq2[i]);
                *(u64t*)&k_s[(o0+i)*130 + n0 + 2*j] = add2(ka[i][j], bk2[i]);
            }
        __syncthreads();

        // --- logits += q @ k^T, packed along reduction dim ---
        u64t lacc[4][4];
        #pragma unroll
        for (int i = 0; i < 4; i++)
            #pragma unroll
            for (int j = 0; j < 4; j++) lacc[i][j] = 0ull;

        #pragma unroll 4
        for (int np = 0; np < NT/2; ++np) {
            u64t q2[4], k2[4];
            #pragma unroll
            for (int i = 0; i < 4; i++) q2[i] = *(const u64t*)&q_s[(o0+i)*130 + 2*np];
            #pragma unroll
            for (int j = 0; j < 4; j++) k2[j] = *(const u64t*)&k_s[(p0+j)*130 + 2*np];
            #pragma unroll
            for (int i = 0; i < 4; i++)
                #pragma unroll
                for (int j = 0; j < 4; j++)
                    lacc[i][j] = fma2(q2[i], k2[j], lacc[i][j]);
        }

        float* Lg = g_logits + b*C8*C8;
        #pragma unroll
        for (int i = 0; i < 4; i++)
            #pragma unroll
            for (int j = 0; j < 4; j++) {
                float lo, hi; unpack2(lacc[i][j], lo, hi);
                atomicAdd(&Lg[(o0+i)*C8 + p0 + j], lo + hi);
            }
        __syncthreads();  // protect q_s/k_s vs next item's x_s writes
    }
}

// -------------------------------------------------------------------------
__global__ void finalize_kernel(const float* __restrict__ wv,
                                const float* __restrict__ bv,
                                float* __restrict__ out)
{
    __shared__ float vmean_s[C8];
    __shared__ float attn_s[C8][C8 + 1];
    const int b = blockIdx.x;
    const int t = threadIdx.x;  // 0..63

    const float* xs = g_xsum + b*CC;
    float acc = 0.f;
    for (int c = 0; c < CC; ++c) acc += wv[t*CC + c] * xs[c];
    vmean_s[t] = acc * (1.f / NPIX) + bv[t];

    const float* Lg = g_logits + b*C8*C8;
    float col[C8];
    float m = -1e30f;
    #pragma unroll
    for (int o = 0; o < C8; ++o) { col[o] = Lg[o*C8 + t]; m = fmaxf(m, col[o]); }
    float s = 0.f;
    #pragma unroll
    for (int o = 0; o < C8; ++o) { col[o] = expf(col[o] - m); s += col[o]; }
    float inv = 1.f / s;
    #pragma unroll
    for (int o = 0; o < C8; ++o) attn_s[o][t] = col[o] * inv;
    __syncthreads();

    float r = 0.f;
    #pragma unroll
    for (int p = 0; p < C8; ++p) r += attn_s[t][p] * vmean_s[p];
    out[b*C8 + t] = r;
}

// -------------------------------------------------------------------------
extern "C" void kernel_launch(void* const* d_in, const int* in_sizes, int n_in,
                              void* d_out, int out_size) {
    const float* x  = (const float*)d_in[0];
    const float* wq = (const float*)d_in[1];
    const float* bq = (const float*)d_in[2];
    const float* wk = (const float*)d_in[3];
    const float* bk = (const float*)d_in[4];
    const float* wv = (const float*)d_in[5];
    const float* bv = (const float*)d_in[6];
    float* out = (float*)d_out;

    cudaFuncSetAttribute(logits_kernel,
                         cudaFuncAttributeMaxDynamicSharedMemorySize, SMEM_BYTES);

    prep_kernel<<<128, 256>>>(wq, wk);
    logits_kernel<<<296, 256, SMEM_BYTES>>>(x, bq, bk);
    finalize_kernel<<<BB, C8>>>(wv, bv, out);
}